// round 1
// baseline (speedup 1.0000x reference)
#include <cuda_runtime.h>

#define TX 32
#define TY 16
#define HX (TX + 4)   // 36: tile width + halo
#define HY (TY + 4)   // 20: tile height + halo
#define DD 128
#define NT (TX * TY)  // 512 threads

__device__ double g_acc;

__global__ void k_zero() { g_acc = 0.0; }

__global__ void __launch_bounds__(NT) k_ssim(const float* __restrict__ x,
                                             const float* __restrict__ y) {
    // separable 1D Gaussian weights, normalized (sum over 3D product == 1)
    constexpr float W0 = 0.120078385f;
    constexpr float W1 = 0.233880764f;
    constexpr float W2 = 0.292081722f;
    constexpr float C1 = 1e-4f;   // 0.01^2
    constexpr float C2 = 9e-4f;   // 0.03^2

    __shared__ float sF[5][HY][HX];   // raw fields, with halo
    __shared__ float sG[5][HY][TX];   // after x-conv
    __shared__ float sred[NT / 32];

    const int tx = threadIdx.x, ty = threadIdx.y;
    const int t = ty * TX + tx;
    const long base = (long)blockIdx.z * (DD * DD * DD);  // nc in [0,8)
    const int w0 = blockIdx.x * TX;
    const int h0 = blockIdx.y * TY;

    // ring[f][j] = y/x-convolved plane at depth z-4+j  (zeros == zero padding)
    float ring[5][5];
#pragma unroll
    for (int f = 0; f < 5; ++f)
#pragma unroll
        for (int j = 0; j < 5; ++j) ring[f][j] = 0.f;

    float tsum = 0.f;

    for (int z = 0; z < DD + 2; ++z) {
        if (z < DD) {
            // ---- load plane with halo, compute 5 fields ----
            for (int i = t; i < HX * HY; i += NT) {
                int r = i / HX, c = i - r * HX;
                int gh = h0 + r - 2;
                int gw = w0 + c - 2;
                float xv = 0.f, yv = 0.f;
                if ((unsigned)gh < DD && (unsigned)gw < DD) {
                    long idx = base + ((long)z * DD + gh) * DD + gw;
                    xv = (x[idx] + 1.f) * 0.5f;
                    yv = (y[idx] + 1.f) * 0.5f;
                }
                sF[0][r][c] = xv;
                sF[1][r][c] = yv;
                sF[2][r][c] = xv * xv;
                sF[3][r][c] = yv * yv;
                sF[4][r][c] = xv * yv;
            }
            __syncthreads();
            // ---- x-direction 5-tap conv: (HY x TX) outputs ----
            for (int i = t; i < HY * TX; i += NT) {
                int r = i >> 5, c = i & (TX - 1);
#pragma unroll
                for (int f = 0; f < 5; ++f) {
                    float a = sF[f][r][c] + sF[f][r][c + 4];
                    float b = sF[f][r][c + 1] + sF[f][r][c + 3];
                    sG[f][r][c] = W0 * a + W1 * b + W2 * sF[f][r][c + 2];
                }
            }
            __syncthreads();
            // ---- y-direction conv into per-thread plane values ----
            float P[5];
#pragma unroll
            for (int f = 0; f < 5; ++f) {
                float a = sG[f][ty][tx] + sG[f][ty + 4][tx];
                float b = sG[f][ty + 1][tx] + sG[f][ty + 3][tx];
                P[f] = W0 * a + W1 * b + W2 * sG[f][ty + 2][tx];
            }
            // ---- push into ring (static indices -> registers) ----
#pragma unroll
            for (int f = 0; f < 5; ++f) {
                ring[f][0] = ring[f][1];
                ring[f][1] = ring[f][2];
                ring[f][2] = ring[f][3];
                ring[f][3] = ring[f][4];
                ring[f][4] = P[f];
            }
        } else {
            // past the end: shift in zero planes (zero padding in z)
#pragma unroll
            for (int f = 0; f < 5; ++f) {
                ring[f][0] = ring[f][1];
                ring[f][1] = ring[f][2];
                ring[f][2] = ring[f][3];
                ring[f][3] = ring[f][4];
                ring[f][4] = 0.f;
            }
        }
        // ---- finalize depth d = z-2: z-conv + SSIM ----
        if (z >= 2) {
            float v[5];
#pragma unroll
            for (int f = 0; f < 5; ++f) {
                float a = ring[f][0] + ring[f][4];
                float b = ring[f][1] + ring[f][3];
                v[f] = W0 * a + W1 * b + W2 * ring[f][2];
            }
            float mu1 = v[0], mu2 = v[1];
            float mu1s = mu1 * mu1, mu2s = mu2 * mu2, mu12 = mu1 * mu2;
            float s1 = v[2] - mu1s;
            float s2 = v[3] - mu2s;
            float s12 = v[4] - mu12;
            float num = (2.f * mu12 + C1) * (2.f * s12 + C2);
            float den = (mu1s + mu2s + C1) * (s1 + s2 + C2);
            tsum += __fdividef(num, den);
        }
    }

    // ---- block reduction ----
#pragma unroll
    for (int off = 16; off; off >>= 1)
        tsum += __shfl_xor_sync(0xFFFFFFFFu, tsum, off);
    if ((t & 31) == 0) sred[t >> 5] = tsum;
    __syncthreads();
    if (t < NT / 32) {
        float v2 = sred[t];
#pragma unroll
        for (int off = NT / 64; off; off >>= 1)
            v2 += __shfl_xor_sync(0x0000FFFFu, v2, off);
        if (t == 0) atomicAdd(&g_acc, (double)v2);
    }
}

__global__ void k_final(float* out) {
    out[0] = (float)(g_acc * (1.0 / 16777216.0));  // mean over 2*4*128^3 = 2^24
}

extern "C" void kernel_launch(void* const* d_in, const int* in_sizes, int n_in,
                              void* d_out, int out_size) {
    const float* x = (const float*)d_in[0];
    const float* y = (const float*)d_in[1];
    // d_in[2] (gaussian kernel) is separable & channel-identical; weights hardcoded.
    k_zero<<<1, 1>>>();
    dim3 grid(DD / TX, DD / TY, 8);   // (4, 8, 8) = 256 CTAs
    dim3 blk(TX, TY);
    k_ssim<<<grid, blk>>>(x, y);
    k_final<<<1, 1>>>((float*)d_out);
}

// round 2
// speedup vs baseline: 1.1244x; 1.1244x over previous
#include <cuda_runtime.h>

#define TX 32
#define TY 16
#define HX (TX + 4)   // 36: tile width + halo
#define HY (TY + 4)   // 20: tile height + halo
#define DD 128
#define NT (TX * TY)  // 512 threads
#define ZCHUNK 32     // output planes per CTA
#define ZITER (ZCHUNK + 4)

__device__ double g_acc;

__global__ void k_zero() { g_acc = 0.0; }

__global__ void __launch_bounds__(NT, 2) k_ssim(const float* __restrict__ x,
                                                const float* __restrict__ y) {
    constexpr float W0 = 0.120078385f;
    constexpr float W1 = 0.233880764f;
    constexpr float W2 = 0.292081722f;
    constexpr float C1 = 1e-4f;
    constexpr float C2 = 9e-4f;

    __shared__ float sF[5][HY][HX];   // raw fields, with halo
    __shared__ float sG[5][HY][TX];   // after x-conv
    __shared__ float sred[NT / 32];

    const int tx = threadIdx.x, ty = threadIdx.y;
    const int t = ty * TX + tx;
    const int nc = blockIdx.z >> 2;            // which of 8 (n,c) volumes
    const int chunk = blockIdx.z & 3;          // z-chunk
    const int z0 = chunk * ZCHUNK;
    const long base = (long)nc * (DD * DD * DD);
    const int w0 = blockIdx.x * TX;
    const int h0 = blockIdx.y * TY;

    float ring[5][5];
#pragma unroll
    for (int f = 0; f < 5; ++f)
#pragma unroll
        for (int j = 0; j < 5; ++j) ring[f][j] = 0.f;

    float tsum = 0.f;

    for (int zi = 0; zi < ZITER; ++zi) {
        const int zin = z0 + zi - 2;
        float P[5];
        if ((unsigned)zin < DD) {
            // ---- phase 1: load plane with halo, compute 5 fields ----
            // 720 elements over 512 threads: i = t, and i = t+512 (t < 208)
#pragma unroll
            for (int k = 0; k < 2; ++k) {
                int i = t + k * NT;
                if (k == 0 || i < HX * HY) {
                    int r = i / HX, c = i - r * HX;
                    int gh = h0 + r - 2;
                    int gw = w0 + c - 2;
                    float xv = 0.f, yv = 0.f;
                    if ((unsigned)gh < DD && (unsigned)gw < DD) {
                        long idx = base + ((long)zin * DD + gh) * DD + gw;
                        xv = (x[idx] + 1.f) * 0.5f;
                        yv = (y[idx] + 1.f) * 0.5f;
                    }
                    sF[0][r][c] = xv;
                    sF[1][r][c] = yv;
                    sF[2][r][c] = xv * xv;
                    sF[3][r][c] = yv * yv;
                    sF[4][r][c] = xv * yv;
                }
            }
            __syncthreads();
            // ---- phase 2: x-direction conv (HY*TX = 640 outputs) ----
#pragma unroll
            for (int k = 0; k < 2; ++k) {
                int i = t + k * NT;
                if (k == 0 || i < HY * TX) {
                    int r = i >> 5, c = i & (TX - 1);
#pragma unroll
                    for (int f = 0; f < 5; ++f) {
                        float a = sF[f][r][c] + sF[f][r][c + 4];
                        float b = sF[f][r][c + 1] + sF[f][r][c + 3];
                        sG[f][r][c] = W0 * a + W1 * b + W2 * sF[f][r][c + 2];
                    }
                }
            }
            __syncthreads();
            // ---- phase 3: y-direction conv ----
#pragma unroll
            for (int f = 0; f < 5; ++f) {
                float a = sG[f][ty][tx] + sG[f][ty + 4][tx];
                float b = sG[f][ty + 1][tx] + sG[f][ty + 3][tx];
                P[f] = W0 * a + W1 * b + W2 * sG[f][ty + 2][tx];
            }
        } else {
#pragma unroll
            for (int f = 0; f < 5; ++f) P[f] = 0.f;
        }
        // ---- push ring ----
#pragma unroll
        for (int f = 0; f < 5; ++f) {
            ring[f][0] = ring[f][1];
            ring[f][1] = ring[f][2];
            ring[f][2] = ring[f][3];
            ring[f][3] = ring[f][4];
            ring[f][4] = P[f];
        }
        // ---- finalize output depth d = z0 + zi - 4 ----
        if (zi >= 4) {
            float v[5];
#pragma unroll
            for (int f = 0; f < 5; ++f) {
                float a = ring[f][0] + ring[f][4];
                float b = ring[f][1] + ring[f][3];
                v[f] = W0 * a + W1 * b + W2 * ring[f][2];
            }
            float mu1 = v[0], mu2 = v[1];
            float mu1s = mu1 * mu1, mu2s = mu2 * mu2, mu12 = mu1 * mu2;
            float s1 = v[2] - mu1s;
            float s2 = v[3] - mu2s;
            float s12 = v[4] - mu12;
            float num = (2.f * mu12 + C1) * (2.f * s12 + C2);
            float den = (mu1s + mu2s + C1) * (s1 + s2 + C2);
            tsum += __fdividef(num, den);
        }
    }

    // ---- block reduction ----
#pragma unroll
    for (int off = 16; off; off >>= 1)
        tsum += __shfl_xor_sync(0xFFFFFFFFu, tsum, off);
    if ((t & 31) == 0) sred[t >> 5] = tsum;
    __syncthreads();
    if (t < NT / 32) {
        float v2 = sred[t];
#pragma unroll
        for (int off = NT / 64; off; off >>= 1)
            v2 += __shfl_xor_sync(0x0000FFFFu, v2, off);
        if (t == 0) atomicAdd(&g_acc, (double)v2);
    }
}

__global__ void k_final(float* out) {
    out[0] = (float)(g_acc * (1.0 / 16777216.0));
}

extern "C" void kernel_launch(void* const* d_in, const int* in_sizes, int n_in,
                              void* d_out, int out_size) {
    const float* x = (const float*)d_in[0];
    const float* y = (const float*)d_in[1];
    k_zero<<<1, 1>>>();
    dim3 grid(DD / TX, DD / TY, 8 * 4);   // (4, 8, 32) = 1024 CTAs
    dim3 blk(TX, TY);
    k_ssim<<<grid, blk>>>(x, y);
    k_final<<<1, 1>>>((float*)d_out);
}

// round 3
// speedup vs baseline: 2.0691x; 1.8402x over previous
#include <cuda_runtime.h>

#define TX 32
#define TY 8
#define HX (TX + 4)   // 36
#define HY (TY + 4)   // 12
#define DD 128
#define NT (TX * TY)  // 256
#define ZCHUNK 32
#define ZITER (ZCHUNK + 4)
#define P1N (HX * HY) // 432
#define P2N (HX * TY) // 288

__device__ double g_acc;

__global__ void k_zero() { g_acc = 0.0; }

__global__ void __launch_bounds__(NT, 4) k_ssim(const float* __restrict__ x,
                                                const float* __restrict__ y) {
    constexpr float W0 = 0.120078385f;
    constexpr float W1 = 0.233880764f;
    constexpr float W2 = 0.292081722f;
    constexpr float C1 = 1e-4f;
    constexpr float C2 = 9e-4f;

    __shared__ float sF[2][HY][HX];   // raw x', y' with halo
    __shared__ float sG[5][TY][HX];   // y-convolved fields (x halo kept)
    __shared__ float sred[NT / 32];

    const int t = threadIdx.x;
    const int tx = t & 31, ty = t >> 5;
    const int nc = blockIdx.z >> 2;
    const int z0 = (blockIdx.z & 3) * ZCHUNK;
    const int base = nc << 21;               // nc * 128^3
    const int w0 = blockIdx.x * TX;
    const int h0 = blockIdx.y * TY;

    // ---- precompute fixed per-thread P1 geometry (2 items) ----
    const int i0 = t;
    const int r0 = i0 / HX, c0 = i0 - r0 * HX;
    const int i1 = t + NT;                    // valid if < P1N  (t < 176)
    const int r1 = i1 / HX, c1 = i1 - r1 * HX;
    const bool has1 = (i1 < P1N);
    const int gh0 = h0 + r0 - 2, gw0 = w0 + c0 - 2;
    const int gh1 = h0 + r1 - 2, gw1 = w0 + c1 - 2;
    const bool ok0 = ((unsigned)gh0 < DD) & ((unsigned)gw0 < DD);
    const bool ok1 = has1 & ((unsigned)gh1 < DD) & ((unsigned)gw1 < DD);
    const int off0 = base + gh0 * DD + gw0;
    const int off1 = base + gh1 * DD + gw1;

    // ---- precompute P2 geometry: item t, plus item 256+t (t<32 -> r=7,c=t+4) ----
    const int q0r = t / HX, q0c = t - q0r * HX;
    const bool hasq1 = (t < P2N - NT);        // t < 32
    const int q1r = TY - 1, q1c = t + 4;

    float ring[5][5];
#pragma unroll
    for (int f = 0; f < 5; ++f)
#pragma unroll
        for (int j = 0; j < 5; ++j) ring[f][j] = 0.f;

    float tsum = 0.f;

    // ---- prologue prefetch for zi = 0 ----
    float px0 = 0.f, py0 = 0.f, px1 = 0.f, py1 = 0.f;
    {
        int zin = z0 - 2;
        if ((unsigned)zin < DD) {
            int zo = zin << 14;
            if (ok0) { px0 = x[off0 + zo]; py0 = y[off0 + zo]; }
            if (ok1) { px1 = x[off1 + zo]; py1 = y[off1 + zo]; }
        }
    }

#pragma unroll 1
    for (int zi = 0; zi < ZITER; ++zi) {
        const int zin = z0 + zi - 2;
        const bool pvalid = ((unsigned)zin < DD);
        float P[5];
        if (pvalid) {
            // ---- P1: store prefetched plane (affine transform folded) ----
            {
                float xv = px0 * 0.5f + 0.5f, yv = py0 * 0.5f + 0.5f;
                if (!ok0) { xv = 0.f; yv = 0.f; }
                sF[0][r0][c0] = xv;
                sF[1][r0][c0] = yv;
            }
            if (has1) {
                float xv = px1 * 0.5f + 0.5f, yv = py1 * 0.5f + 0.5f;
                if (!ok1) { xv = 0.f; yv = 0.f; }
                sF[0][r1][c1] = xv;
                sF[1][r1][c1] = yv;
            }
        }
        // ---- prefetch next plane (LDGs in flight across barrier/phases) ----
        {
            int nz = zin + 1;
            px0 = py0 = px1 = py1 = 0.f;
            if ((zi + 1 < ZITER) && ((unsigned)nz < DD)) {
                int zo = nz << 14;
                if (ok0) { px0 = x[off0 + zo]; py0 = y[off0 + zo]; }
                if (ok1) { px1 = x[off1 + zo]; py1 = y[off1 + zo]; }
            }
        }
        if (pvalid) {
            __syncthreads();
            // ---- P2: y-direction conv, squares formed at the tap ----
#pragma unroll
            for (int k = 0; k < 2; ++k) {
                int rr, cc;
                bool act;
                if (k == 0) { rr = q0r; cc = q0c; act = true; }
                else        { rr = q1r; cc = q1c; act = hasq1; }
                if (act) {
                    float a0 = 0.f, a1 = 0.f, a2 = 0.f, a3 = 0.f, a4 = 0.f;
#pragma unroll
                    for (int j = 0; j < 5; ++j) {
                        const float wj = (j == 0 || j == 4) ? W0
                                       : (j == 1 || j == 3) ? W1 : W2;
                        float xv = sF[0][rr + j][cc];
                        float yv = sF[1][rr + j][cc];
                        a0 += wj * xv;
                        a1 += wj * yv;
                        a2 += wj * (xv * xv);
                        a3 += wj * (yv * yv);
                        a4 += wj * (xv * yv);
                    }
                    sG[0][rr][cc] = a0;
                    sG[1][rr][cc] = a1;
                    sG[2][rr][cc] = a2;
                    sG[3][rr][cc] = a3;
                    sG[4][rr][cc] = a4;
                }
            }
            __syncthreads();
            // ---- P3: x-direction conv (one output per thread) ----
#pragma unroll
            for (int f = 0; f < 5; ++f) {
                float a = sG[f][ty][tx] + sG[f][ty][tx + 4];
                float b = sG[f][ty][tx + 1] + sG[f][ty][tx + 3];
                P[f] = W0 * a + W1 * b + W2 * sG[f][ty][tx + 2];
            }
        } else {
#pragma unroll
            for (int f = 0; f < 5; ++f) P[f] = 0.f;
        }
        // ---- ring push (z history) ----
#pragma unroll
        for (int f = 0; f < 5; ++f) {
            ring[f][0] = ring[f][1];
            ring[f][1] = ring[f][2];
            ring[f][2] = ring[f][3];
            ring[f][3] = ring[f][4];
            ring[f][4] = P[f];
        }
        // ---- z-conv + SSIM for output depth z0+zi-4 ----
        if (zi >= 4) {
            float v[5];
#pragma unroll
            for (int f = 0; f < 5; ++f) {
                float a = ring[f][0] + ring[f][4];
                float b = ring[f][1] + ring[f][3];
                v[f] = W0 * a + W1 * b + W2 * ring[f][2];
            }
            float mu1 = v[0], mu2 = v[1];
            float mu1s = mu1 * mu1, mu2s = mu2 * mu2, mu12 = mu1 * mu2;
            float s1 = v[2] - mu1s;
            float s2 = v[3] - mu2s;
            float s12 = v[4] - mu12;
            float num = (2.f * mu12 + C1) * (2.f * s12 + C2);
            float den = (mu1s + mu2s + C1) * (s1 + s2 + C2);
            tsum += __fdividef(num, den);
        }
    }

    // ---- block reduction ----
#pragma unroll
    for (int off = 16; off; off >>= 1)
        tsum += __shfl_xor_sync(0xFFFFFFFFu, tsum, off);
    if ((t & 31) == 0) sred[t >> 5] = tsum;
    __syncthreads();
    if (t < NT / 32) {
        float v2 = sred[t];
#pragma unroll
        for (int off = NT / 64; off; off >>= 1)
            v2 += __shfl_xor_sync(0x000000FFu, v2, off);
        if (t == 0) atomicAdd(&g_acc, (double)v2);
    }
}

__global__ void k_final(float* out) {
    out[0] = (float)(g_acc * (1.0 / 16777216.0));
}

extern "C" void kernel_launch(void* const* d_in, const int* in_sizes, int n_in,
                              void* d_out, int out_size) {
    const float* x = (const float*)d_in[0];
    const float* y = (const float*)d_in[1];
    k_zero<<<1, 1>>>();
    dim3 grid(DD / TX, DD / TY, 8 * 4);   // (4, 16, 32) = 2048 CTAs
    dim3 blk(NT);
    k_ssim<<<grid, blk>>>(x, y);
    k_final<<<1, 1>>>((float*)d_out);
}